// round 6
// baseline (speedup 1.0000x reference)
#include <cuda_runtime.h>
#include <cstdint>

#define NUSERS 100000
#define NITEMS 50000
#define EMBED 64
#define RREL 3
#define NNZ_E 1000000
#define IG_NNZ_E 500000
#define BB 512
#define KK 100
#define EPSF 1e-8f
#define SCORE2_SCALE (0.5f/3.0f)
#define L2C 1e-4f

#define IE (NITEMS*EMBED)        // floats per relation plane
#define UBW 3200                 // user bitmap words
#define IBW 1600                 // item bitmap words
#define NIG (RREL*NITEMS)        // 150000 ig segments
#define SCAN_B 512

// ---------------- device scratch (static, allocation-free) ----------------
__device__ __align__(16) float g_item_agg[RREL*IE];
__device__ __align__(16) float g_item_feat[IE];
__device__ __align__(16) float g_item_featW[IE];
__device__ __align__(16) float g_ig_deg[NIG];
__device__ __align__(16) int   g_map[NUSERS];
__device__ __align__(16) unsigned g_ubit[UBW];
__device__ __align__(16) unsigned g_ibit[IBW];
__device__ __align__(16) unsigned g_nbit[IBW];
__device__ __align__(16) float g_udeg[RREL*BB];
__device__ __align__(16) float g_uacc[RREL*BB*128];
__device__ __align__(16) float g_proj[RREL*BB*128];
__device__ __align__(16) float g_u2[BB*EMBED];
__device__ __align__(16) int2  g_crel[RREL*NNZ_E];    // compacted (slot,col)
__device__ int g_cnt_rel[RREL];
__device__ double g_l2i;
// CSR machinery
__device__ __align__(16) int  g_cnt_ig[NIG];     // hist -> exclusive offsets
__device__ __align__(16) int  g_cur_ig[NIG];     // fill cursors
__device__ __align__(16) int2 g_csr_ig[RREL*IG_NNZ_E];  // (col, val bits)
__device__ __align__(16) int  g_cnt_tr[NITEMS];
__device__ __align__(16) int  g_cur_tr[NITEMS];
__device__ __align__(16) int  g_csr_tr[NNZ_E];   // user row ids
__device__ int g_bsum[1024];

__device__ __forceinline__ void red_add_v4(float* addr, float4 v) {
    asm volatile("red.global.add.v4.f32 [%0], {%1,%2,%3,%4};"
                 :: "l"(addr), "f"(v.x), "f"(v.y), "f"(v.z), "f"(v.w) : "memory");
}

// ---------------- one-shot zero (no big embedding planes!) ----------------
__global__ void k_zero() {
    int idx = blockIdx.x * blockDim.x + threadIdx.x;   // covers NIG
    float4 z4 = make_float4(0.f,0.f,0.f,0.f);
    if (idx < NIG)             g_cnt_ig[idx] = 0;
    if (idx < NITEMS)          g_cnt_tr[idx] = 0;
    if (idx < RREL*BB*128/4)   reinterpret_cast<float4*>(g_uacc)[idx] = z4;
    if (idx < RREL*BB)         g_udeg[idx] = 0.f;
    if (idx < NUSERS/4)        reinterpret_cast<int4*>(g_map)[idx] = make_int4(-1,-1,-1,-1);
    if (idx < UBW)             g_ubit[idx] = 0u;
    if (idx < IBW)             { g_ibit[idx] = 0u; g_nbit[idx] = 0u; }
    if (idx < RREL)            g_cnt_rel[idx] = 0;
    if (idx == 0)              g_l2i = 0.0;
}

// ---------------- build maps / bitmaps ----------------
__global__ void k_map(const int* __restrict__ user, const int* __restrict__ item) {
    int idx = blockIdx.x * blockDim.x + threadIdx.x;
    if (idx < BB) {
        int uid = user[idx];
        g_map[uid] = idx;
        atomicOr(&g_ubit[uid >> 5], 1u << (uid & 31));
    }
    if (idx < BB*KK) {
        int it = item[idx];
        atomicOr(&g_ibit[it >> 5], 1u << (it & 31));
        atomicOr(&g_nbit[it >> 5], 1u << (it & 31));
    }
}

// ---------------- histograms ----------------
__global__ void k_hist_ig(const int* __restrict__ rows_all) {
    int r = blockIdx.y;
    int e = blockIdx.x * blockDim.x + threadIdx.x;
    if (e >= IG_NNZ_E) return;
    int row = __ldg(rows_all + (size_t)r*IG_NNZ_E + e);
    atomicAdd(&g_cnt_ig[r*NITEMS + row], 1);
}
__global__ void k_hist_tr(const int* __restrict__ cols) {
    int e = blockIdx.x * blockDim.x + threadIdx.x;
    if (e >= NNZ_E) return;
    atomicAdd(&g_cnt_tr[__ldg(cols + e)], 1);
}

// ---------------- hierarchical exclusive scan (3 kernels) ----------------
__global__ void k_scan_local(int* __restrict__ data, int n) {
    __shared__ int s[SCAN_B];
    int tid = threadIdx.x;
    int i = blockIdx.x * SCAN_B + tid;
    int v = (i < n) ? data[i] : 0;
    s[tid] = v;
    __syncthreads();
    #pragma unroll
    for (int off = 1; off < SCAN_B; off <<= 1) {
        int t = (tid >= off) ? s[tid - off] : 0;
        __syncthreads();
        s[tid] += t;
        __syncthreads();
    }
    int incl = s[tid];
    if (i < n) data[i] = incl - v;             // exclusive
    if (tid == SCAN_B-1) g_bsum[blockIdx.x] = incl;
}
__global__ void k_scan_bsum(int nb) {          // single block, nb <= 512
    __shared__ int s[SCAN_B];
    int tid = threadIdx.x;
    int v = (tid < nb) ? g_bsum[tid] : 0;
    s[tid] = v;
    __syncthreads();
    #pragma unroll
    for (int off = 1; off < SCAN_B; off <<= 1) {
        int t = (tid >= off) ? s[tid - off] : 0;
        __syncthreads();
        s[tid] += t;
        __syncthreads();
    }
    if (tid < nb) g_bsum[tid] = s[tid] - v;    // exclusive
}
__global__ void k_scan_add(int* __restrict__ data, int* __restrict__ cursor, int n) {
    int i = blockIdx.x * SCAN_B + threadIdx.x;
    if (i < n) {
        int v = data[i] + g_bsum[blockIdx.x];
        data[i] = v;
        cursor[i] = v;
    }
}

// ---------------- CSR fill ----------------
__global__ void k_fill_ig(const int* __restrict__ rows_all, const int* __restrict__ cols_all,
                          const float* __restrict__ vals_all) {
    int r = blockIdx.y;
    int e = blockIdx.x * blockDim.x + threadIdx.x;
    if (e >= IG_NNZ_E) return;
    size_t off = (size_t)r*IG_NNZ_E + e;
    int row = __ldg(rows_all + off);
    int col = __ldg(cols_all + off);
    float v = __ldg(vals_all + off);
    int pos = atomicAdd(&g_cur_ig[r*NITEMS + row], 1);
    g_csr_ig[pos] = make_int2(col, __float_as_int(v));
}
__global__ void k_fill_tr(const int* __restrict__ rows, const int* __restrict__ cols) {
    int e = blockIdx.x * blockDim.x + threadIdx.x;
    if (e >= NNZ_E) return;
    int col = __ldg(cols + e);
    int row = __ldg(rows + e);
    int pos = atomicAdd(&g_cur_tr[col], 1);
    g_csr_tr[pos] = row;
}

// ---------------- prescan rel edges: warp-aggregated compaction ----------------
__global__ void k_prescan_rel(const int* __restrict__ rows_all, const int* __restrict__ cols_all) {
    int r = blockIdx.y;
    const int* rows = rows_all + (size_t)r*NNZ_E;
    const int* cols = cols_all + (size_t)r*NNZ_E;
    int g = blockIdx.x * blockDim.x + threadIdx.x;
    int lane = threadIdx.x & 31;
    bool inrange = (g < NNZ_E/4);
    int e0 = g * 4;
    int4 rr = inrange ? *reinterpret_cast<const int4*>(rows + e0) : make_int4(0,0,0,0);
    #pragma unroll
    for (int q = 0; q < 4; q++) {
        int row = (q==0)?rr.x:(q==1)?rr.y:(q==2)?rr.z:rr.w;
        bool pass = false;
        if (inrange) {
            unsigned w = __ldg(&g_ubit[row >> 5]);
            pass = (w >> (row & 31)) & 1u;
        }
        unsigned m = __ballot_sync(0xffffffffu, pass);
        if (m == 0) continue;
        int cnt = __popc(m);
        int leader = __ffs(m) - 1;
        int base = 0;
        if (lane == leader) base = atomicAdd(&g_cnt_rel[r], cnt);
        base = __shfl_sync(0xffffffffu, base, leader);
        if (pass) {
            int rank = __popc(m & ((1u << lane) - 1u));
            int slot = g_map[row];
            int col = __ldg(&cols[e0 + q]);
            g_crel[(size_t)r*NNZ_E + base + rank] = make_int2(slot, col);
            atomicAdd(&g_udeg[r*BB + slot], 1.0f);
            atomicOr(&g_nbit[col >> 5], 1u << (col & 31));
        }
    }
}

// ---------------- gather: item_agg rows (needed only), no atomics ----------------
__global__ void k_gather_ig(const float* __restrict__ item_emb) {
    int t = blockIdx.x * blockDim.x + threadIdx.x;
    int unit = t >> 4;                 // unit = r*NITEMS + row
    if (unit >= NIG) return;
    int p = t & 15;
    int row = unit % NITEMS;
    if (!((__ldg(&g_nbit[row >> 5]) >> (row & 31)) & 1u)) return;
    int start = __ldg(&g_cnt_ig[unit]);
    int end = (unit + 1 < NIG) ? __ldg(&g_cnt_ig[unit + 1]) : RREL*IG_NNZ_E;
    const float4* E = reinterpret_cast<const float4*>(item_emb);
    float4 acc = make_float4(0.f,0.f,0.f,0.f);
    float dsum = 0.f;
    for (int e = start; e < end; e++) {
        int2 cv = __ldg(&g_csr_ig[e]);
        float v = __int_as_float(cv.y);
        float4 x = E[(size_t)cv.x*16 + p];
        acc.x += v*x.x; acc.y += v*x.y; acc.z += v*x.z; acc.w += v*x.w;
        dsum += v;
    }
    reinterpret_cast<float4*>(g_item_agg)[(size_t)unit*16 + p] = acc;
    if (p == 0) g_ig_deg[unit] = dsum;
}

// ---------------- gather: item_feat rows (batch items only), no atomics -------
__global__ void k_gather_tr(const float* __restrict__ user_emb) {
    int t = blockIdx.x * blockDim.x + threadIdx.x;
    int row = t >> 4;
    if (row >= NITEMS) return;
    int p = t & 15;
    if (!((__ldg(&g_ibit[row >> 5]) >> (row & 31)) & 1u)) return;
    int start = __ldg(&g_cnt_tr[row]);
    int end = (row + 1 < NITEMS) ? __ldg(&g_cnt_tr[row + 1]) : NNZ_E;
    const float4* U = reinterpret_cast<const float4*>(user_emb);
    float4 acc = make_float4(0.f,0.f,0.f,0.f);
    for (int e = start; e < end; e++) {
        int urow = __ldg(&g_csr_tr[e]);
        float4 x = U[(size_t)urow*16 + p];
        acc.x += x.x; acc.y += x.y; acc.z += x.z; acc.w += x.w;
    }
    reinterpret_cast<float4*>(g_item_feat)[(size_t)row*16 + p] = acc;
}

// ---------------- (NITEMS x 64) @ (64 x 64), batch-item rows only ----------------
__global__ void k_matmul_featW(const float* __restrict__ Wm) {
    __shared__ float4 w_s[64*16];
    __shared__ float4 a_s[16*16];
    int tid = threadIdx.x;          // 256
    const float4* W4 = reinterpret_cast<const float4*>(Wm);
    for (int t = tid; t < 64*16; t += 256) w_s[t] = W4[t];
    __syncthreads();
    int r = tid >> 4, j = tid & 15;
    for (int chunk = blockIdx.x; chunk < NITEMS/16; chunk += gridDim.x) {
        int row0 = chunk * 16;
        unsigned wbits = (g_ibit[row0 >> 5] >> (row0 & 31)) & 0xFFFFu;
        if (wbits == 0u) continue;
        a_s[r*16 + j] = reinterpret_cast<const float4*>(g_item_feat)[(row0 + r)*16 + j];
        __syncthreads();
        float4 acc = make_float4(0.f,0.f,0.f,0.f);
        #pragma unroll
        for (int kk = 0; kk < 16; kk++) {
            float4 a  = a_s[r*16 + kk];
            float4 w0 = w_s[(4*kk+0)*16 + j];
            float4 w1 = w_s[(4*kk+1)*16 + j];
            float4 w2 = w_s[(4*kk+2)*16 + j];
            float4 w3 = w_s[(4*kk+3)*16 + j];
            acc.x += a.x*w0.x + a.y*w1.x + a.z*w2.x + a.w*w3.x;
            acc.y += a.x*w0.y + a.y*w1.y + a.z*w2.y + a.w*w3.y;
            acc.z += a.x*w0.z + a.y*w1.z + a.z*w2.z + a.w*w3.z;
            acc.w += a.x*w0.w + a.y*w1.w + a.z*w2.w + a.w*w3.w;
        }
        if ((wbits >> r) & 1u)
            reinterpret_cast<float4*>(g_item_featW)[(row0 + r)*16 + j] = acc;
        __syncthreads();
    }
}

// ---------------- heavy rel accumulation over compacted entries ----------------
__global__ void k_rel_heavy(const float* __restrict__ item_emb) {
    int r = blockIdx.y;
    int ne = g_cnt_rel[r];
    const int2* lst = g_crel + (size_t)r*NNZ_E;
    const float4* agg4 = reinterpret_cast<const float4*>(g_item_agg + (size_t)r*IE);
    const float* deg = g_ig_deg + (size_t)r*NITEMS;
    int p = threadIdx.x & 15;
    int lane_entry = (blockIdx.x * blockDim.x + threadIdx.x) >> 4;
    int stride = (gridDim.x * blockDim.x) >> 4;
    for (int idx = lane_entry; idx < ne; idx += stride) {
        int2 ent = lst[idx];
        int slot = ent.x, col = ent.y;
        float4 ie = reinterpret_cast<const float4*>(item_emb)[(size_t)col*16 + p];
        float4 ag = agg4[(size_t)col*16 + p];
        float inv = 1.0f / (__ldg(&deg[col]) + EPSF);
        ag.x *= inv; ag.y *= inv; ag.z *= inv; ag.w *= inv;
        float* dst = g_uacc + ((size_t)r*BB + slot)*128;
        red_add_v4(dst + p*4, ie);
        red_add_v4(dst + 64 + p*4, ag);
    }
}

// ---------------- proj with Wp folding; outputs [proj1 | Wp@proj2] ----------------
__global__ void k_proj(const float* __restrict__ Wb_all, const float* __restrict__ Wp_all) {
    __shared__ float s_in[128], s_mid[128], s_pr[128];
    int r = blockIdx.y, slot = blockIdx.x, j = threadIdx.x;   // 128 thr
    const float* Wb = Wb_all + (size_t)r*128*128;
    const float* Wp = Wp_all + (size_t)r*64*64;
    float inv = 1.0f / (g_udeg[r*BB + slot] + EPSF);
    s_in[j] = g_uacc[((size_t)r*BB + slot)*128 + j] * inv;
    __syncthreads();
    if (j < 64) {
        s_mid[j] = s_in[j];
    } else {
        int m = j - 64;
        float a = 0.f;
        #pragma unroll 8
        for (int k = 0; k < 64; k++) a += s_in[64+k] * Wp[k*64 + m];
        s_mid[j] = a;
    }
    __syncthreads();
    float pr = 0.f;
    #pragma unroll 8
    for (int k = 0; k < 128; k++) pr += s_mid[k] * Wb[k*128 + j];
    s_pr[j] = pr;
    __syncthreads();
    float outv;
    if (j < 64) {
        outv = pr;
    } else {
        int k = j - 64;
        float a = 0.f;
        #pragma unroll 8
        for (int jj = 0; jj < 64; jj++) a += Wp[k*64 + jj] * s_pr[64+jj];
        outv = a;   // projB[k] = (Wp @ proj2)[k]
    }
    g_proj[((size_t)r*BB + slot)*128 + j] = outv;
}

// ---------------- u2 = user_feature @ W (weights/totals folded) ----------------
__global__ void k_userW(const float* __restrict__ Wm, const float* __restrict__ mgnn) {
    __shared__ float uf[64];
    int slot = blockIdx.x, j = threadIdx.x;
    float m0 = mgnn[0], m1 = mgnn[1], m2 = mgnn[2];
    float d0 = g_udeg[slot], d1 = g_udeg[BB+slot], d2 = g_udeg[2*BB+slot];
    float total = m0*d0 + m1*d1 + m2*d2;
    float c0 = m0*d0/(d0+EPSF), c1 = m1*d1/(d1+EPSF), c2 = m2*d2/(d2+EPSF);
    float v = c0*g_uacc[(size_t)slot*128 + j]
            + c1*g_uacc[((size_t)BB+slot)*128 + j]
            + c2*g_uacc[((size_t)2*BB+slot)*128 + j];
    uf[j] = v / (total + EPSF);
    __syncthreads();
    float acc = 0.f;
    #pragma unroll 8
    for (int k = 0; k < 64; k++) acc += uf[k] * Wm[k*64 + j];
    g_u2[slot*64 + j] = acc;
}

// ---------------- fused score1 + score2 + item L2 ----------------
__global__ void k_score(const int* __restrict__ user, const int* __restrict__ item,
                        const float* __restrict__ user_emb, const float* __restrict__ item_emb,
                        float* __restrict__ out) {
    int idx = blockIdx.x * blockDim.x + threadIdx.x;
    float n2 = 0.f;
    if (idx < BB*KK) {
        int b = idx / KK;
        int uid = user[b];
        int slot = g_map[uid];
        int it = item[idx];
        const float4* ue  = reinterpret_cast<const float4*>(user_emb) + (size_t)uid*16;
        const float4* u2  = reinterpret_cast<const float4*>(g_u2) + (size_t)slot*16;
        const float4* ie  = reinterpret_cast<const float4*>(item_emb) + (size_t)it*16;
        const float4* ifw = reinterpret_cast<const float4*>(g_item_featW) + (size_t)it*16;
        float s = 0.f;
        float4 ier[16];
        #pragma unroll
        for (int t = 0; t < 16; t++) {
            float4 a = ue[t], c = ie[t];
            ier[t] = c;
            s  += a.x*c.x + a.y*c.y + a.z*c.z + a.w*c.w;
            n2 += c.x*c.x + c.y*c.y + c.z*c.z + c.w*c.w;
        }
        #pragma unroll
        for (int t = 0; t < 16; t++) {
            float4 a = u2[t], c = ifw[t];
            s  += a.x*c.x + a.y*c.y + a.z*c.z + a.w*c.w;
            n2 += c.x*c.x + c.y*c.y + c.z*c.z + c.w*c.w;
        }
        float s2 = 0.f;
        #pragma unroll
        for (int r = 0; r < RREL; r++) {
            const float4* pr = reinterpret_cast<const float4*>(g_proj) + ((size_t)r*BB + slot)*32;
            const float4* ag = reinterpret_cast<const float4*>(g_item_agg + (size_t)r*IE) + (size_t)it*16;
            float dinv = 1.0f / (g_ig_deg[r*NITEMS + it] + EPSF);
            #pragma unroll
            for (int t = 0; t < 16; t++) {
                float4 a = pr[t], c = ier[t];
                s2 += a.x*c.x + a.y*c.y + a.z*c.z + a.w*c.w;
            }
            #pragma unroll
            for (int t = 0; t < 16; t++) {
                float4 a = pr[16+t], c = ag[t];
                s2 += dinv * (a.x*c.x + a.y*c.y + a.z*c.z + a.w*c.w);
            }
        }
        out[idx] = s + SCORE2_SCALE * s2;
    }
    __shared__ float red[256];
    red[threadIdx.x] = n2;
    __syncthreads();
    for (int s = 128; s > 0; s >>= 1) {
        if (threadIdx.x < s) red[threadIdx.x] += red[threadIdx.x + s];
        __syncthreads();
    }
    if (threadIdx.x == 0) atomicAdd(&g_l2i, (double)red[0]);
}

// ---------------- user-side L2 + final output element ----------------
__global__ void k_l2final(const int* __restrict__ user, const float* __restrict__ user_emb,
                          float* __restrict__ out, int out_n) {
    int b = threadIdx.x;   // 512
    int uid = user[b];
    int slot = g_map[uid];
    const float4* ue = reinterpret_cast<const float4*>(user_emb) + (size_t)uid*16;
    const float4* u2 = reinterpret_cast<const float4*>(g_u2) + (size_t)slot*16;
    float n2 = 0.f;
    #pragma unroll
    for (int t = 0; t < 16; t++) {
        float4 a = ue[t]; n2 += a.x*a.x + a.y*a.y + a.z*a.z + a.w*a.w;
        float4 c = u2[t]; n2 += c.x*c.x + c.y*c.y + c.z*c.z + c.w*c.w;
    }
    __shared__ float red[512];
    red[b] = n2;
    __syncthreads();
    for (int s = 256; s > 0; s >>= 1) {
        if (b < s) red[b] += red[b + s];
        __syncthreads();
    }
    if (b == 0 && out_n > BB*KK) {
        out[BB*KK] = (float)((double)L2C * ((double)KK * (double)red[0] + g_l2i));
    }
}

// ---------------- launch ----------------
extern "C" void kernel_launch(void* const* d_in, const int* in_sizes, int n_in,
                              void* d_out, int out_size) {
    const int*   user       = (const int*)  d_in[0];
    const int*   item       = (const int*)  d_in[1];
    const int*   rel_rows   = (const int*)  d_in[2];
    const int*   rel_cols   = (const int*)  d_in[3];
    const int*   ig_rows    = (const int*)  d_in[4];
    const int*   ig_cols    = (const int*)  d_in[5];
    const float* ig_vals    = (const float*)d_in[6];
    const int*   train_rows = (const int*)  d_in[7];
    const int*   train_cols = (const int*)  d_in[8];
    const float* user_emb   = (const float*)d_in[9];
    const float* item_emb   = (const float*)d_in[10];
    const float* mgnn       = (const float*)d_in[11];
    const float* Wb         = (const float*)d_in[12];
    const float* Wp         = (const float*)d_in[13];
    const float* Wm         = (const float*)d_in[14];
    float* out = (float*)d_out;

    int* p_cnt_ig; cudaGetSymbolAddress((void**)&p_cnt_ig, g_cnt_ig);
    int* p_cur_ig; cudaGetSymbolAddress((void**)&p_cur_ig, g_cur_ig);
    int* p_cnt_tr; cudaGetSymbolAddress((void**)&p_cnt_tr, g_cnt_tr);
    int* p_cur_tr; cudaGetSymbolAddress((void**)&p_cur_tr, g_cur_tr);

    k_zero<<<(NIG + 255)/256, 256>>>();
    k_map<<<(BB*KK + 255)/256, 256>>>(user, item);

    // histograms
    {
        dim3 grid((IG_NNZ_E + 255)/256, RREL);
        k_hist_ig<<<grid, 256>>>(ig_rows);
    }
    k_hist_tr<<<(NNZ_E + 255)/256, 256>>>(train_cols);

    // prescan rel (needs map; writes nbit before gather_ig)
    {
        dim3 grid((NNZ_E/4 + 255)/256, RREL);
        k_prescan_rel<<<grid, 256>>>(rel_rows, rel_cols);
    }

    // scans: ig (150000 -> 293 blocks), train (50000 -> 98 blocks)
    const int NB_IG = (NIG + SCAN_B - 1)/SCAN_B;
    const int NB_TR = (NITEMS + SCAN_B - 1)/SCAN_B;
    k_scan_local<<<NB_IG, SCAN_B>>>(p_cnt_ig, NIG);
    k_scan_bsum<<<1, SCAN_B>>>(NB_IG);
    k_scan_add<<<NB_IG, SCAN_B>>>(p_cnt_ig, p_cur_ig, NIG);
    k_scan_local<<<NB_TR, SCAN_B>>>(p_cnt_tr, NITEMS);
    k_scan_bsum<<<1, SCAN_B>>>(NB_TR);
    k_scan_add<<<NB_TR, SCAN_B>>>(p_cnt_tr, p_cur_tr, NITEMS);

    // CSR fill
    {
        dim3 grid((IG_NNZ_E + 255)/256, RREL);
        k_fill_ig<<<grid, 256>>>(ig_rows, ig_cols, ig_vals);
    }
    k_fill_tr<<<(NNZ_E + 255)/256, 256>>>(train_rows, train_cols);

    // gathers (atomic-free)
    k_gather_ig<<<(NIG*16 + 255)/256, 256>>>(item_emb);
    k_gather_tr<<<(NITEMS*16 + 255)/256, 256>>>(user_emb);

    k_matmul_featW<<<512, 256>>>(Wm);

    {
        dim3 grid(128, RREL);
        k_rel_heavy<<<grid, 256>>>(item_emb);
    }
    {
        dim3 grid(BB, RREL);
        k_proj<<<grid, 128>>>(Wb, Wp);
    }
    k_userW<<<BB, EMBED>>>(Wm, mgnn);

    k_score<<<(BB*KK + 255)/256, 256>>>(user, item, user_emb, item_emb, out);
    k_l2final<<<1, BB>>>(user, user_emb, out, out_size);
}

// round 7
// speedup vs baseline: 1.0124x; 1.0124x over previous
#include <cuda_runtime.h>
#include <cstdint>

#define NUSERS 100000
#define NITEMS 50000
#define EMBED 64
#define RREL 3
#define NNZ_E 1000000
#define IG_NNZ_E 500000
#define BB 512
#define KK 100
#define EPSF 1e-8f
#define SCORE2_SCALE (0.5f/3.0f)
#define L2C 1e-4f

#define IE (NITEMS*EMBED)        // 3,200,000 floats per relation plane
#define UBW 3200                 // user bitmap words
#define IBW 1600                 // item bitmap words

// ---------------- device scratch (static, allocation-free) ----------------
__device__ __align__(16) float g_item_agg[RREL*IE];
__device__ __align__(16) float g_item_feat[IE];
__device__ __align__(16) float g_item_featW[IE];
__device__ __align__(16) float g_ig_deg[RREL*NITEMS];
__device__ __align__(16) int   g_map[NUSERS];
__device__ __align__(16) unsigned g_ubit[UBW];
__device__ __align__(16) unsigned g_ibit[IBW];
__device__ __align__(16) unsigned g_nbit[IBW];
__device__ __align__(16) float g_udeg[RREL*BB];
__device__ __align__(16) float g_uacc[RREL*BB*128];
__device__ __align__(16) float g_proj[RREL*BB*128];
__device__ __align__(16) float g_u2[BB*EMBED];
__device__ __align__(16) int2  g_crel[RREL*NNZ_E];    // compacted (slot,col)
__device__ int g_cnt_rel[RREL];
__device__ double g_l2i;

__device__ __forceinline__ void red_add_v4(float* addr, float4 v) {
    asm volatile("red.global.add.v4.f32 [%0], {%1,%2,%3,%4};"
                 :: "l"(addr), "f"(v.x), "f"(v.y), "f"(v.z), "f"(v.w) : "memory");
}

// ---------------- one-shot zero ----------------
__global__ void k_zero() {
    int idx = blockIdx.x * blockDim.x + threadIdx.x;
    float4 z4 = make_float4(0.f,0.f,0.f,0.f);
    if (idx < RREL*IE/4)       reinterpret_cast<float4*>(g_item_agg)[idx] = z4;
    if (idx < IE/4)            reinterpret_cast<float4*>(g_item_feat)[idx] = z4;
    if (idx < RREL*NITEMS/4)   reinterpret_cast<float4*>(g_ig_deg)[idx] = z4;
    if (idx < RREL*BB*128/4)   reinterpret_cast<float4*>(g_uacc)[idx] = z4;
    if (idx < RREL*BB)         g_udeg[idx] = 0.f;
    if (idx < NUSERS/4)        reinterpret_cast<int4*>(g_map)[idx] = make_int4(-1,-1,-1,-1);
    if (idx < UBW)             g_ubit[idx] = 0u;
    if (idx < IBW)             { g_ibit[idx] = 0u; g_nbit[idx] = 0u; }
    if (idx < RREL)            g_cnt_rel[idx] = 0;
    if (idx == 0)              g_l2i = 0.0;
}

// ---------------- build maps / bitmaps ----------------
__global__ void k_map(const int* __restrict__ user, const int* __restrict__ item) {
    int idx = blockIdx.x * blockDim.x + threadIdx.x;
    if (idx < BB) {
        int uid = user[idx];
        g_map[uid] = idx;
        atomicOr(&g_ubit[uid >> 5], 1u << (uid & 31));
    }
    if (idx < BB*KK) {
        int it = item[idx];
        atomicOr(&g_ibit[it >> 5], 1u << (it & 31));
        atomicOr(&g_nbit[it >> 5], 1u << (it & 31));
    }
}

// ---------------- prescan rel edges: warp-aggregated compaction ----------------
__global__ void k_prescan_rel(const int* __restrict__ rows_all, const int* __restrict__ cols_all) {
    int r = blockIdx.y;
    const int* rows = rows_all + (size_t)r*NNZ_E;
    const int* cols = cols_all + (size_t)r*NNZ_E;
    int g = blockIdx.x * blockDim.x + threadIdx.x;
    int lane = threadIdx.x & 31;
    bool inrange = (g < NNZ_E/4);
    int e0 = g * 4;
    int4 rr = inrange ? *reinterpret_cast<const int4*>(rows + e0) : make_int4(0,0,0,0);
    #pragma unroll
    for (int q = 0; q < 4; q++) {
        int row = (q==0)?rr.x:(q==1)?rr.y:(q==2)?rr.z:rr.w;
        bool pass = false;
        if (inrange) {
            unsigned w = __ldg(&g_ubit[row >> 5]);
            pass = (w >> (row & 31)) & 1u;
        }
        unsigned m = __ballot_sync(0xffffffffu, pass);
        if (m == 0) continue;
        int cnt = __popc(m);
        int leader = __ffs(m) - 1;
        int base = 0;
        if (lane == leader) base = atomicAdd(&g_cnt_rel[r], cnt);
        base = __shfl_sync(0xffffffffu, base, leader);
        if (pass) {
            int rank = __popc(m & ((1u << lane) - 1u));
            int slot = g_map[row];
            int col = __ldg(&cols[e0 + q]);
            g_crel[(size_t)r*NNZ_E + base + rank] = make_int2(slot, col);
            atomicAdd(&g_udeg[r*BB + slot], 1.0f);
            atomicOr(&g_nbit[col >> 5], 1u << (col & 31));
        }
    }
}

// ---------------- item-graph scatter (needed rows), 8 edges / 16-thr group ----
__global__ void k_ig(const int* __restrict__ rows_all, const int* __restrict__ cols_all,
                     const float* __restrict__ vals_all, const float* __restrict__ item_emb) {
    int r = blockIdx.y;
    const int*   rows = rows_all + (size_t)r*IG_NNZ_E;
    const int*   cols = cols_all + (size_t)r*IG_NNZ_E;
    const float* vals = vals_all + (size_t)r*IG_NNZ_E;
    float* agg = g_item_agg + (size_t)r*IE;
    float* deg = g_ig_deg + (size_t)r*NITEMS;

    int t = blockIdx.x * blockDim.x + threadIdx.x;
    int g = t >> 4;
    if (g >= IG_NNZ_E/8) return;
    int p = t & 15;
    int e0 = g * 8;
    int4  rrA = *reinterpret_cast<const int4*>(rows + e0);
    int4  rrB = *reinterpret_cast<const int4*>(rows + e0 + 4);
    int4   cA = *reinterpret_cast<const int4*>(cols + e0);
    int4   cB = *reinterpret_cast<const int4*>(cols + e0 + 4);
    float4 vA = *reinterpret_cast<const float4*>(vals + e0);
    float4 vB = *reinterpret_cast<const float4*>(vals + e0 + 4);
    int   rw[8] = {rrA.x, rrA.y, rrA.z, rrA.w, rrB.x, rrB.y, rrB.z, rrB.w};
    int   cl[8] = {cA.x, cA.y, cA.z, cA.w, cB.x, cB.y, cB.z, cB.w};
    float vv[8] = {vA.x, vA.y, vA.z, vA.w, vB.x, vB.y, vB.z, vB.w};
    const float4* E = reinterpret_cast<const float4*>(item_emb);
    bool nd[8];
    #pragma unroll
    for (int q = 0; q < 8; q++)
        nd[q] = (__ldg(&g_nbit[rw[q] >> 5]) >> (rw[q] & 31)) & 1u;
    float4 x[8];
    #pragma unroll
    for (int q = 0; q < 8; q++)
        if (nd[q]) x[q] = E[(size_t)cl[q]*16 + p];
    #pragma unroll
    for (int q = 0; q < 8; q++)
        if (nd[q]) {
            float v = vv[q];
            float4 y = x[q];
            y.x*=v; y.y*=v; y.z*=v; y.w*=v;
            red_add_v4(agg + (size_t)rw[q]*64 + p*4, y);
        }
    if (p == 0) {
        #pragma unroll
        for (int q = 0; q < 8; q++)
            if (nd[q]) atomicAdd(deg + rw[q], vv[q]);
    }
}

// ---------------- fused train filter + scatter, 8 edges / 16-thr group ----
__global__ void k_train_fused(const int* __restrict__ rows, const int* __restrict__ cols,
                              const float* __restrict__ user_emb) {
    int t = blockIdx.x * blockDim.x + threadIdx.x;
    int g = t >> 4;
    if (g >= NNZ_E/8) return;
    int p = t & 15;
    int e0 = g * 8;
    int4 ccA = *reinterpret_cast<const int4*>(cols + e0);
    int4 ccB = *reinterpret_cast<const int4*>(cols + e0 + 4);
    int4 rrA = *reinterpret_cast<const int4*>(rows + e0);
    int4 rrB = *reinterpret_cast<const int4*>(rows + e0 + 4);
    int cc[8] = {ccA.x, ccA.y, ccA.z, ccA.w, ccB.x, ccB.y, ccB.z, ccB.w};
    int rr[8] = {rrA.x, rrA.y, rrA.z, rrA.w, rrB.x, rrB.y, rrB.z, rrB.w};
    const float4* E = reinterpret_cast<const float4*>(user_emb);
    bool bd[8];
    #pragma unroll
    for (int q = 0; q < 8; q++)
        bd[q] = (__ldg(&g_ibit[cc[q] >> 5]) >> (cc[q] & 31)) & 1u;
    float4 x[8];
    #pragma unroll
    for (int q = 0; q < 8; q++)
        if (bd[q]) x[q] = E[(size_t)rr[q]*16 + p];
    #pragma unroll
    for (int q = 0; q < 8; q++)
        if (bd[q]) red_add_v4(g_item_feat + (size_t)cc[q]*64 + p*4, x[q]);
}

// ---------------- (NITEMS x 64) @ (64 x 64), batch-item rows only ----------------
__global__ void k_matmul_featW(const float* __restrict__ Wm) {
    __shared__ float4 w_s[64*16];
    __shared__ float4 a_s[16*16];
    int tid = threadIdx.x;          // 256
    const float4* W4 = reinterpret_cast<const float4*>(Wm);
    for (int t = tid; t < 64*16; t += 256) w_s[t] = W4[t];
    __syncthreads();
    int r = tid >> 4, j = tid & 15;
    for (int chunk = blockIdx.x; chunk < NITEMS/16; chunk += gridDim.x) {
        int row0 = chunk * 16;
        unsigned wbits = (g_ibit[row0 >> 5] >> (row0 & 31)) & 0xFFFFu;
        if (wbits == 0u) continue;
        a_s[r*16 + j] = reinterpret_cast<const float4*>(g_item_feat)[(row0 + r)*16 + j];
        __syncthreads();
        float4 acc = make_float4(0.f,0.f,0.f,0.f);
        #pragma unroll
        for (int kk = 0; kk < 16; kk++) {
            float4 a  = a_s[r*16 + kk];
            float4 w0 = w_s[(4*kk+0)*16 + j];
            float4 w1 = w_s[(4*kk+1)*16 + j];
            float4 w2 = w_s[(4*kk+2)*16 + j];
            float4 w3 = w_s[(4*kk+3)*16 + j];
            acc.x += a.x*w0.x + a.y*w1.x + a.z*w2.x + a.w*w3.x;
            acc.y += a.x*w0.y + a.y*w1.y + a.z*w2.y + a.w*w3.y;
            acc.z += a.x*w0.z + a.y*w1.z + a.z*w2.z + a.w*w3.z;
            acc.w += a.x*w0.w + a.y*w1.w + a.z*w2.w + a.w*w3.w;
        }
        if ((wbits >> r) & 1u)
            reinterpret_cast<float4*>(g_item_featW)[(row0 + r)*16 + j] = acc;
        __syncthreads();
    }
}

// ---------------- heavy rel accumulation over compacted entries ----------------
__global__ void k_rel_heavy(const float* __restrict__ item_emb) {
    int r = blockIdx.y;
    int ne = g_cnt_rel[r];
    const int2* lst = g_crel + (size_t)r*NNZ_E;
    const float4* agg4 = reinterpret_cast<const float4*>(g_item_agg + (size_t)r*IE);
    const float* deg = g_ig_deg + (size_t)r*NITEMS;
    int p = threadIdx.x & 15;
    int lane_entry = (blockIdx.x * blockDim.x + threadIdx.x) >> 4;
    int stride = (gridDim.x * blockDim.x) >> 4;
    for (int idx = lane_entry; idx < ne; idx += stride) {
        int2 ent = lst[idx];
        int slot = ent.x, col = ent.y;
        float4 ie = reinterpret_cast<const float4*>(item_emb)[(size_t)col*16 + p];
        float4 ag = agg4[(size_t)col*16 + p];
        float inv = 1.0f / (__ldg(&deg[col]) + EPSF);
        ag.x *= inv; ag.y *= inv; ag.z *= inv; ag.w *= inv;
        float* dst = g_uacc + ((size_t)r*BB + slot)*128;
        red_add_v4(dst + p*4, ie);
        red_add_v4(dst + 64 + p*4, ag);
    }
}

// ---------------- proj with Wp folding; outputs [proj1 | Wp@proj2] ----------------
__global__ void k_proj(const float* __restrict__ Wb_all, const float* __restrict__ Wp_all) {
    __shared__ float s_in[128], s_mid[128], s_pr[128];
    int r = blockIdx.y, slot = blockIdx.x, j = threadIdx.x;   // 128 thr
    const float* Wb = Wb_all + (size_t)r*128*128;
    const float* Wp = Wp_all + (size_t)r*64*64;
    float inv = 1.0f / (g_udeg[r*BB + slot] + EPSF);
    s_in[j] = g_uacc[((size_t)r*BB + slot)*128 + j] * inv;
    __syncthreads();
    if (j < 64) {
        s_mid[j] = s_in[j];
    } else {
        int m = j - 64;
        float a = 0.f;
        #pragma unroll 8
        for (int k = 0; k < 64; k++) a += s_in[64+k] * Wp[k*64 + m];
        s_mid[j] = a;
    }
    __syncthreads();
    float pr = 0.f;
    #pragma unroll 8
    for (int k = 0; k < 128; k++) pr += s_mid[k] * Wb[k*128 + j];
    s_pr[j] = pr;
    __syncthreads();
    float outv;
    if (j < 64) {
        outv = pr;
    } else {
        int k = j - 64;
        float a = 0.f;
        #pragma unroll 8
        for (int jj = 0; jj < 64; jj++) a += Wp[k*64 + jj] * s_pr[64+jj];
        outv = a;   // projB[k] = (Wp @ proj2)[k]
    }
    g_proj[((size_t)r*BB + slot)*128 + j] = outv;
}

// ---------------- u2 = user_feature @ W (weights/totals folded) ----------------
__global__ void k_userW(const float* __restrict__ Wm, const float* __restrict__ mgnn) {
    __shared__ float uf[64];
    int slot = blockIdx.x, j = threadIdx.x;
    float m0 = mgnn[0], m1 = mgnn[1], m2 = mgnn[2];
    float d0 = g_udeg[slot], d1 = g_udeg[BB+slot], d2 = g_udeg[2*BB+slot];
    float total = m0*d0 + m1*d1 + m2*d2;
    float c0 = m0*d0/(d0+EPSF), c1 = m1*d1/(d1+EPSF), c2 = m2*d2/(d2+EPSF);
    float v = c0*g_uacc[(size_t)slot*128 + j]
            + c1*g_uacc[((size_t)BB+slot)*128 + j]
            + c2*g_uacc[((size_t)2*BB+slot)*128 + j];
    uf[j] = v / (total + EPSF);
    __syncthreads();
    float acc = 0.f;
    #pragma unroll 8
    for (int k = 0; k < 64; k++) acc += uf[k] * Wm[k*64 + j];
    g_u2[slot*64 + j] = acc;
}

// ---------------- fused score1 + score2 + item L2 ----------------
__global__ void k_score(const int* __restrict__ user, const int* __restrict__ item,
                        const float* __restrict__ user_emb, const float* __restrict__ item_emb,
                        float* __restrict__ out) {
    int idx = blockIdx.x * blockDim.x + threadIdx.x;
    float n2 = 0.f;
    if (idx < BB*KK) {
        int b = idx / KK;
        int uid = user[b];
        int slot = g_map[uid];
        int it = item[idx];
        const float4* ue  = reinterpret_cast<const float4*>(user_emb) + (size_t)uid*16;
        const float4* u2  = reinterpret_cast<const float4*>(g_u2) + (size_t)slot*16;
        const float4* ie  = reinterpret_cast<const float4*>(item_emb) + (size_t)it*16;
        const float4* ifw = reinterpret_cast<const float4*>(g_item_featW) + (size_t)it*16;
        float s = 0.f;
        float4 ier[16];
        #pragma unroll
        for (int t = 0; t < 16; t++) {
            float4 a = ue[t], c = ie[t];
            ier[t] = c;
            s  += a.x*c.x + a.y*c.y + a.z*c.z + a.w*c.w;
            n2 += c.x*c.x + c.y*c.y + c.z*c.z + c.w*c.w;
        }
        #pragma unroll
        for (int t = 0; t < 16; t++) {
            float4 a = u2[t], c = ifw[t];
            s  += a.x*c.x + a.y*c.y + a.z*c.z + a.w*c.w;
            n2 += c.x*c.x + c.y*c.y + c.z*c.z + c.w*c.w;
        }
        float s2 = 0.f;
        #pragma unroll
        for (int r = 0; r < RREL; r++) {
            const float4* pr = reinterpret_cast<const float4*>(g_proj) + ((size_t)r*BB + slot)*32;
            const float4* ag = reinterpret_cast<const float4*>(g_item_agg + (size_t)r*IE) + (size_t)it*16;
            float dinv = 1.0f / (g_ig_deg[r*NITEMS + it] + EPSF);
            #pragma unroll
            for (int t = 0; t < 16; t++) {
                float4 a = pr[t], c = ier[t];
                s2 += a.x*c.x + a.y*c.y + a.z*c.z + a.w*c.w;
            }
            #pragma unroll
            for (int t = 0; t < 16; t++) {
                float4 a = pr[16+t], c = ag[t];
                s2 += dinv * (a.x*c.x + a.y*c.y + a.z*c.z + a.w*c.w);
            }
        }
        out[idx] = s + SCORE2_SCALE * s2;
    }
    __shared__ float red[256];
    red[threadIdx.x] = n2;
    __syncthreads();
    for (int s = 128; s > 0; s >>= 1) {
        if (threadIdx.x < s) red[threadIdx.x] += red[threadIdx.x + s];
        __syncthreads();
    }
    if (threadIdx.x == 0) atomicAdd(&g_l2i, (double)red[0]);
}

// ---------------- user-side L2 + final output element ----------------
__global__ void k_l2final(const int* __restrict__ user, const float* __restrict__ user_emb,
                          float* __restrict__ out, int out_n) {
    int b = threadIdx.x;   // 512
    int uid = user[b];
    int slot = g_map[uid];
    const float4* ue = reinterpret_cast<const float4*>(user_emb) + (size_t)uid*16;
    const float4* u2 = reinterpret_cast<const float4*>(g_u2) + (size_t)slot*16;
    float n2 = 0.f;
    #pragma unroll
    for (int t = 0; t < 16; t++) {
        float4 a = ue[t]; n2 += a.x*a.x + a.y*a.y + a.z*a.z + a.w*a.w;
        float4 c = u2[t]; n2 += c.x*c.x + c.y*c.y + c.z*c.z + c.w*c.w;
    }
    __shared__ float red[512];
    red[b] = n2;
    __syncthreads();
    for (int s = 256; s > 0; s >>= 1) {
        if (b < s) red[b] += red[b + s];
        __syncthreads();
    }
    if (b == 0 && out_n > BB*KK) {
        out[BB*KK] = (float)((double)L2C * ((double)KK * (double)red[0] + g_l2i));
    }
}

// ---------------- launch ----------------
extern "C" void kernel_launch(void* const* d_in, const int* in_sizes, int n_in,
                              void* d_out, int out_size) {
    const int*   user       = (const int*)  d_in[0];
    const int*   item       = (const int*)  d_in[1];
    const int*   rel_rows   = (const int*)  d_in[2];
    const int*   rel_cols   = (const int*)  d_in[3];
    const int*   ig_rows    = (const int*)  d_in[4];
    const int*   ig_cols    = (const int*)  d_in[5];
    const float* ig_vals    = (const float*)d_in[6];
    const int*   train_rows = (const int*)  d_in[7];
    const int*   train_cols = (const int*)  d_in[8];
    const float* user_emb   = (const float*)d_in[9];
    const float* item_emb   = (const float*)d_in[10];
    const float* mgnn       = (const float*)d_in[11];
    const float* Wb         = (const float*)d_in[12];
    const float* Wp         = (const float*)d_in[13];
    const float* Wm         = (const float*)d_in[14];
    float* out = (float*)d_out;

    k_zero<<<(RREL*IE/4 + 255)/256, 256>>>();
    k_map<<<(BB*KK + 255)/256, 256>>>(user, item);

    {
        dim3 grid((NNZ_E/4 + 255)/256, RREL);
        k_prescan_rel<<<grid, 256>>>(rel_rows, rel_cols);
    }

    {
        dim3 grid((IG_NNZ_E/8*16 + 255)/256, RREL);
        k_ig<<<grid, 256>>>(ig_rows, ig_cols, ig_vals, item_emb);
    }
    k_train_fused<<<(NNZ_E/8*16 + 255)/256, 256>>>(train_rows, train_cols, user_emb);

    k_matmul_featW<<<512, 256>>>(Wm);

    {
        dim3 grid(128, RREL);
        k_rel_heavy<<<grid, 256>>>(item_emb);
    }
    {
        dim3 grid(BB, RREL);
        k_proj<<<grid, 128>>>(Wb, Wp);
    }
    k_userW<<<BB, EMBED>>>(Wm, mgnn);

    k_score<<<(BB*KK + 255)/256, 256>>>(user, item, user_emb, item_emb, out);
    k_l2final<<<1, BB>>>(user, user_emb, out, out_size);
}

// round 8
// speedup vs baseline: 1.0853x; 1.0719x over previous
#include <cuda_runtime.h>
#include <cstdint>

#define NUSERS 100000
#define NITEMS 50000
#define EMBED 64
#define RREL 3
#define NNZ_E 1000000
#define IG_NNZ_E 500000
#define BB 512
#define KK 100
#define EPSF 1e-8f
#define SCORE2_SCALE (0.5f/3.0f)
#define L2C 1e-4f

#define IE (NITEMS*EMBED)
#define UBW 3200
#define IBW 1600

// flattened-grid segment sizes for k_scatter
#define NB_IG 7813                 // ceil(500000/4*16 / 256) per relation
#define NB_TR 15625                // 1000000/4*16 / 256
#define NB_SCATTER (RREL*NB_IG + NB_TR)
// k_mid segments
#define NB_MM 512
#define NB_RH 128
#define NB_MID (NB_MM + RREL*NB_RH)

// ---------------- device scratch (static, allocation-free) ----------------
__device__ __align__(16) float g_item_agg[RREL*IE];
__device__ __align__(16) float g_item_feat[IE];
__device__ __align__(16) float g_item_featW[IE];
__device__ __align__(16) float g_ig_deg[RREL*NITEMS];
__device__ __align__(16) int   g_map[NUSERS];
__device__ __align__(16) unsigned g_ubit[UBW];
__device__ __align__(16) unsigned g_ibit[IBW];
__device__ __align__(16) unsigned g_nbit[IBW];
__device__ __align__(16) float g_udeg[RREL*BB];
__device__ __align__(16) float g_uacc[RREL*BB*128];
__device__ __align__(16) float g_proj[RREL*BB*128];
__device__ __align__(16) float g_u2[BB*EMBED];
__device__ __align__(16) int2  g_crel[RREL*NNZ_E];
__device__ int g_cnt_rel[RREL];
__device__ double g_l2i;

__device__ __forceinline__ void red_add_v4(float* addr, float4 v) {
    asm volatile("red.global.add.v4.f32 [%0], {%1,%2,%3,%4};"
                 :: "l"(addr), "f"(v.x), "f"(v.y), "f"(v.z), "f"(v.w) : "memory");
}

// ---------------- one-shot zero ----------------
__global__ void k_zero() {
    int idx = blockIdx.x * blockDim.x + threadIdx.x;
    float4 z4 = make_float4(0.f,0.f,0.f,0.f);
    if (idx < RREL*IE/4)       reinterpret_cast<float4*>(g_item_agg)[idx] = z4;
    if (idx < IE/4)            reinterpret_cast<float4*>(g_item_feat)[idx] = z4;
    if (idx < RREL*NITEMS/4)   reinterpret_cast<float4*>(g_ig_deg)[idx] = z4;
    if (idx < RREL*BB*128/4)   reinterpret_cast<float4*>(g_uacc)[idx] = z4;
    if (idx < RREL*BB)         g_udeg[idx] = 0.f;
    if (idx < NUSERS/4)        reinterpret_cast<int4*>(g_map)[idx] = make_int4(-1,-1,-1,-1);
    if (idx < UBW)             g_ubit[idx] = 0u;
    if (idx < IBW)             { g_ibit[idx] = 0u; g_nbit[idx] = 0u; }
    if (idx < RREL)            g_cnt_rel[idx] = 0;
    if (idx == 0)              g_l2i = 0.0;
}

// ---------------- build maps / bitmaps ----------------
__global__ void k_map(const int* __restrict__ user, const int* __restrict__ item) {
    int idx = blockIdx.x * blockDim.x + threadIdx.x;
    if (idx < BB) {
        int uid = user[idx];
        g_map[uid] = idx;
        atomicOr(&g_ubit[uid >> 5], 1u << (uid & 31));
    }
    if (idx < BB*KK) {
        int it = item[idx];
        atomicOr(&g_ibit[it >> 5], 1u << (it & 31));
        atomicOr(&g_nbit[it >> 5], 1u << (it & 31));
    }
}

// ---------------- prescan rel edges: warp-aggregated compaction ----------------
__global__ void k_prescan_rel(const int* __restrict__ rows_all, const int* __restrict__ cols_all) {
    int r = blockIdx.y;
    const int* rows = rows_all + (size_t)r*NNZ_E;
    const int* cols = cols_all + (size_t)r*NNZ_E;
    int g = blockIdx.x * blockDim.x + threadIdx.x;
    int lane = threadIdx.x & 31;
    bool inrange = (g < NNZ_E/4);
    int e0 = g * 4;
    int4 rr = inrange ? *reinterpret_cast<const int4*>(rows + e0) : make_int4(0,0,0,0);
    #pragma unroll
    for (int q = 0; q < 4; q++) {
        int row = (q==0)?rr.x:(q==1)?rr.y:(q==2)?rr.z:rr.w;
        bool pass = false;
        if (inrange) {
            unsigned w = __ldg(&g_ubit[row >> 5]);
            pass = (w >> (row & 31)) & 1u;
        }
        unsigned m = __ballot_sync(0xffffffffu, pass);
        if (m == 0) continue;
        int cnt = __popc(m);
        int leader = __ffs(m) - 1;
        int base = 0;
        if (lane == leader) base = atomicAdd(&g_cnt_rel[r], cnt);
        base = __shfl_sync(0xffffffffu, base, leader);
        if (pass) {
            int rank = __popc(m & ((1u << lane) - 1u));
            int slot = g_map[row];
            int col = __ldg(&cols[e0 + q]);
            g_crel[(size_t)r*NNZ_E + base + rank] = make_int2(slot, col);
            atomicAdd(&g_udeg[r*BB + slot], 1.0f);
            atomicOr(&g_nbit[col >> 5], 1u << (col & 31));
        }
    }
}

// ---------------- fused scatter: ig (3 relations) + train in ONE kernel --------
__global__ void k_scatter(const int* __restrict__ ig_rows_all, const int* __restrict__ ig_cols_all,
                          const float* __restrict__ ig_vals_all, const float* __restrict__ item_emb,
                          const int* __restrict__ tr_rows, const int* __restrict__ tr_cols,
                          const float* __restrict__ user_emb) {
    int bx = blockIdx.x;
    if (bx < RREL*NB_IG) {
        // ---- ig segment ----
        int r = bx / NB_IG;
        int bxx = bx - r*NB_IG;
        const int*   rows = ig_rows_all + (size_t)r*IG_NNZ_E;
        const int*   cols = ig_cols_all + (size_t)r*IG_NNZ_E;
        const float* vals = ig_vals_all + (size_t)r*IG_NNZ_E;
        float* agg = g_item_agg + (size_t)r*IE;
        float* deg = g_ig_deg + (size_t)r*NITEMS;
        int t = bxx * 256 + threadIdx.x;
        int g = t >> 4;
        if (g >= IG_NNZ_E/4) return;
        int p = t & 15;
        int e0 = g * 4;
        int4  rr = *reinterpret_cast<const int4*>(rows + e0);
        int4   c = *reinterpret_cast<const int4*>(cols + e0);
        float4 v = *reinterpret_cast<const float4*>(vals + e0);
        const float4* E = reinterpret_cast<const float4*>(item_emb);
        bool n0 = (__ldg(&g_nbit[rr.x >> 5]) >> (rr.x & 31)) & 1u;
        bool n1 = (__ldg(&g_nbit[rr.y >> 5]) >> (rr.y & 31)) & 1u;
        bool n2 = (__ldg(&g_nbit[rr.z >> 5]) >> (rr.z & 31)) & 1u;
        bool n3 = (__ldg(&g_nbit[rr.w >> 5]) >> (rr.w & 31)) & 1u;
        if (n0) { float4 x = E[(size_t)c.x*16 + p]; x.x*=v.x; x.y*=v.x; x.z*=v.x; x.w*=v.x;
                  red_add_v4(agg + (size_t)rr.x*64 + p*4, x); }
        if (n1) { float4 x = E[(size_t)c.y*16 + p]; x.x*=v.y; x.y*=v.y; x.z*=v.y; x.w*=v.y;
                  red_add_v4(agg + (size_t)rr.y*64 + p*4, x); }
        if (n2) { float4 x = E[(size_t)c.z*16 + p]; x.x*=v.z; x.y*=v.z; x.z*=v.z; x.w*=v.z;
                  red_add_v4(agg + (size_t)rr.z*64 + p*4, x); }
        if (n3) { float4 x = E[(size_t)c.w*16 + p]; x.x*=v.w; x.y*=v.w; x.z*=v.w; x.w*=v.w;
                  red_add_v4(agg + (size_t)rr.w*64 + p*4, x); }
        if (p == 0) {
            if (n0) atomicAdd(deg + rr.x, v.x);
            if (n1) atomicAdd(deg + rr.y, v.y);
            if (n2) atomicAdd(deg + rr.z, v.z);
            if (n3) atomicAdd(deg + rr.w, v.w);
        }
    } else {
        // ---- train segment ----
        int bxx = bx - RREL*NB_IG;
        int t = bxx * 256 + threadIdx.x;
        int g = t >> 4;
        if (g >= NNZ_E/4) return;
        int p = t & 15;
        int e0 = g * 4;
        int4 cc = *reinterpret_cast<const int4*>(tr_cols + e0);
        int4 rr = *reinterpret_cast<const int4*>(tr_rows + e0);
        const float4* E = reinterpret_cast<const float4*>(user_emb);
        bool b0 = (__ldg(&g_ibit[cc.x >> 5]) >> (cc.x & 31)) & 1u;
        bool b1 = (__ldg(&g_ibit[cc.y >> 5]) >> (cc.y & 31)) & 1u;
        bool b2 = (__ldg(&g_ibit[cc.z >> 5]) >> (cc.z & 31)) & 1u;
        bool b3 = (__ldg(&g_ibit[cc.w >> 5]) >> (cc.w & 31)) & 1u;
        if (b0) { float4 x = E[(size_t)rr.x*16 + p]; red_add_v4(g_item_feat + (size_t)cc.x*64 + p*4, x); }
        if (b1) { float4 x = E[(size_t)rr.y*16 + p]; red_add_v4(g_item_feat + (size_t)cc.y*64 + p*4, x); }
        if (b2) { float4 x = E[(size_t)rr.z*16 + p]; red_add_v4(g_item_feat + (size_t)cc.z*64 + p*4, x); }
        if (b3) { float4 x = E[(size_t)rr.w*16 + p]; red_add_v4(g_item_feat + (size_t)cc.w*64 + p*4, x); }
    }
}

// ---------------- fused mid: matmul_featW + rel_heavy --------------------------
__global__ void k_mid(const float* __restrict__ Wm, const float* __restrict__ item_emb) {
    int bx = blockIdx.x;
    if (bx < NB_MM) {
        // ---- (NITEMS x 64) @ (64 x 64), batch-item rows only ----
        __shared__ float4 w_s[64*16];
        __shared__ float4 a_s[16*16];
        int tid = threadIdx.x;
        const float4* W4 = reinterpret_cast<const float4*>(Wm);
        for (int t = tid; t < 64*16; t += 256) w_s[t] = W4[t];
        __syncthreads();
        int r = tid >> 4, j = tid & 15;
        for (int chunk = bx; chunk < NITEMS/16; chunk += NB_MM) {
            int row0 = chunk * 16;
            unsigned wbits = (g_ibit[row0 >> 5] >> (row0 & 31)) & 0xFFFFu;
            if (wbits == 0u) continue;
            a_s[r*16 + j] = reinterpret_cast<const float4*>(g_item_feat)[(row0 + r)*16 + j];
            __syncthreads();
            float4 acc = make_float4(0.f,0.f,0.f,0.f);
            #pragma unroll
            for (int kk = 0; kk < 16; kk++) {
                float4 a  = a_s[r*16 + kk];
                float4 w0 = w_s[(4*kk+0)*16 + j];
                float4 w1 = w_s[(4*kk+1)*16 + j];
                float4 w2 = w_s[(4*kk+2)*16 + j];
                float4 w3 = w_s[(4*kk+3)*16 + j];
                acc.x += a.x*w0.x + a.y*w1.x + a.z*w2.x + a.w*w3.x;
                acc.y += a.x*w0.y + a.y*w1.y + a.z*w2.y + a.w*w3.y;
                acc.z += a.x*w0.z + a.y*w1.z + a.z*w2.z + a.w*w3.z;
                acc.w += a.x*w0.w + a.y*w1.w + a.z*w2.w + a.w*w3.w;
            }
            if ((wbits >> r) & 1u)
                reinterpret_cast<float4*>(g_item_featW)[(row0 + r)*16 + j] = acc;
            __syncthreads();
        }
    } else {
        // ---- rel_heavy over compacted entries ----
        int bb = bx - NB_MM;
        int r = bb / NB_RH;
        int bxx = bb - r*NB_RH;
        int ne = g_cnt_rel[r];
        const int2* lst = g_crel + (size_t)r*NNZ_E;
        const float4* agg4 = reinterpret_cast<const float4*>(g_item_agg + (size_t)r*IE);
        const float* deg = g_ig_deg + (size_t)r*NITEMS;
        int p = threadIdx.x & 15;
        int lane_entry = (bxx * 256 + threadIdx.x) >> 4;
        const int stride = (NB_RH * 256) >> 4;     // 2048
        for (int idx = lane_entry; idx < ne; idx += stride) {
            int2 ent = lst[idx];
            int slot = ent.x, col = ent.y;
            float4 ie = reinterpret_cast<const float4*>(item_emb)[(size_t)col*16 + p];
            float4 ag = agg4[(size_t)col*16 + p];
            float inv = 1.0f / (__ldg(&deg[col]) + EPSF);
            ag.x *= inv; ag.y *= inv; ag.z *= inv; ag.w *= inv;
            float* dst = g_uacc + ((size_t)r*BB + slot)*128;
            red_add_v4(dst + p*4, ie);
            red_add_v4(dst + 64 + p*4, ag);
        }
    }
}

// ---------------- proj (y<3) + userW (y==3) ----------------
__global__ void k_proj(const float* __restrict__ Wb_all, const float* __restrict__ Wp_all,
                       const float* __restrict__ Wm, const float* __restrict__ mgnn) {
    if (blockIdx.y == RREL) {
        // ---- u2 = user_feature @ W ----
        __shared__ float uf[64];
        int slot = blockIdx.x, j = threadIdx.x;
        if (j < 64) {
            float m0 = mgnn[0], m1 = mgnn[1], m2 = mgnn[2];
            float d0 = g_udeg[slot], d1 = g_udeg[BB+slot], d2 = g_udeg[2*BB+slot];
            float total = m0*d0 + m1*d1 + m2*d2;
            float c0 = m0*d0/(d0+EPSF), c1 = m1*d1/(d1+EPSF), c2 = m2*d2/(d2+EPSF);
            float v = c0*g_uacc[(size_t)slot*128 + j]
                    + c1*g_uacc[((size_t)BB+slot)*128 + j]
                    + c2*g_uacc[((size_t)2*BB+slot)*128 + j];
            uf[j] = v / (total + EPSF);
        }
        __syncthreads();
        if (j < 64) {
            float acc = 0.f;
            #pragma unroll 8
            for (int k = 0; k < 64; k++) acc += uf[k] * Wm[k*64 + j];
            g_u2[slot*64 + j] = acc;
        }
        return;
    }
    __shared__ float s_in[128], s_mid[128], s_pr[128];
    int r = blockIdx.y, slot = blockIdx.x, j = threadIdx.x;
    const float* Wb = Wb_all + (size_t)r*128*128;
    const float* Wp = Wp_all + (size_t)r*64*64;
    float inv = 1.0f / (g_udeg[r*BB + slot] + EPSF);
    s_in[j] = g_uacc[((size_t)r*BB + slot)*128 + j] * inv;
    __syncthreads();
    if (j < 64) {
        s_mid[j] = s_in[j];
    } else {
        int m = j - 64;
        float a = 0.f;
        #pragma unroll 8
        for (int k = 0; k < 64; k++) a += s_in[64+k] * Wp[k*64 + m];
        s_mid[j] = a;
    }
    __syncthreads();
    float pr = 0.f;
    #pragma unroll 8
    for (int k = 0; k < 128; k++) pr += s_mid[k] * Wb[k*128 + j];
    s_pr[j] = pr;
    __syncthreads();
    float outv;
    if (j < 64) {
        outv = pr;
    } else {
        int k = j - 64;
        float a = 0.f;
        #pragma unroll 8
        for (int jj = 0; jj < 64; jj++) a += Wp[k*64 + jj] * s_pr[64+jj];
        outv = a;
    }
    g_proj[((size_t)r*BB + slot)*128 + j] = outv;
}

// ---------------- fused score1 + score2 + item L2 ----------------
__global__ void k_score(const int* __restrict__ user, const int* __restrict__ item,
                        const float* __restrict__ user_emb, const float* __restrict__ item_emb,
                        float* __restrict__ out) {
    int idx = blockIdx.x * blockDim.x + threadIdx.x;
    float n2 = 0.f;
    if (idx < BB*KK) {
        int b = idx / KK;
        int uid = user[b];
        int slot = g_map[uid];
        int it = item[idx];
        const float4* ue  = reinterpret_cast<const float4*>(user_emb) + (size_t)uid*16;
        const float4* u2  = reinterpret_cast<const float4*>(g_u2) + (size_t)slot*16;
        const float4* ie  = reinterpret_cast<const float4*>(item_emb) + (size_t)it*16;
        const float4* ifw = reinterpret_cast<const float4*>(g_item_featW) + (size_t)it*16;
        float s = 0.f;
        float4 ier[16];
        #pragma unroll
        for (int t = 0; t < 16; t++) {
            float4 a = ue[t], c = ie[t];
            ier[t] = c;
            s  += a.x*c.x + a.y*c.y + a.z*c.z + a.w*c.w;
            n2 += c.x*c.x + c.y*c.y + c.z*c.z + c.w*c.w;
        }
        #pragma unroll
        for (int t = 0; t < 16; t++) {
            float4 a = u2[t], c = ifw[t];
            s  += a.x*c.x + a.y*c.y + a.z*c.z + a.w*c.w;
            n2 += c.x*c.x + c.y*c.y + c.z*c.z + c.w*c.w;
        }
        float s2 = 0.f;
        #pragma unroll
        for (int r = 0; r < RREL; r++) {
            const float4* pr = reinterpret_cast<const float4*>(g_proj) + ((size_t)r*BB + slot)*32;
            const float4* ag = reinterpret_cast<const float4*>(g_item_agg + (size_t)r*IE) + (size_t)it*16;
            float dinv = 1.0f / (g_ig_deg[r*NITEMS + it] + EPSF);
            #pragma unroll
            for (int t = 0; t < 16; t++) {
                float4 a = pr[t], c = ier[t];
                s2 += a.x*c.x + a.y*c.y + a.z*c.z + a.w*c.w;
            }
            #pragma unroll
            for (int t = 0; t < 16; t++) {
                float4 a = pr[16+t], c = ag[t];
                s2 += dinv * (a.x*c.x + a.y*c.y + a.z*c.z + a.w*c.w);
            }
        }
        out[idx] = s + SCORE2_SCALE * s2;
    }
    __shared__ float red[256];
    red[threadIdx.x] = n2;
    __syncthreads();
    for (int s = 128; s > 0; s >>= 1) {
        if (threadIdx.x < s) red[threadIdx.x] += red[threadIdx.x + s];
        __syncthreads();
    }
    if (threadIdx.x == 0) atomicAdd(&g_l2i, (double)red[0]);
}

// ---------------- user-side L2 + final output element ----------------
__global__ void k_l2final(const int* __restrict__ user, const float* __restrict__ user_emb,
                          float* __restrict__ out, int out_n) {
    int b = threadIdx.x;   // 512
    int uid = user[b];
    int slot = g_map[uid];
    const float4* ue = reinterpret_cast<const float4*>(user_emb) + (size_t)uid*16;
    const float4* u2 = reinterpret_cast<const float4*>(g_u2) + (size_t)slot*16;
    float n2 = 0.f;
    #pragma unroll
    for (int t = 0; t < 16; t++) {
        float4 a = ue[t]; n2 += a.x*a.x + a.y*a.y + a.z*a.z + a.w*a.w;
        float4 c = u2[t]; n2 += c.x*c.x + c.y*c.y + c.z*c.z + c.w*c.w;
    }
    __shared__ float red[512];
    red[b] = n2;
    __syncthreads();
    for (int s = 256; s > 0; s >>= 1) {
        if (b < s) red[b] += red[b + s];
        __syncthreads();
    }
    if (b == 0 && out_n > BB*KK) {
        out[BB*KK] = (float)((double)L2C * ((double)KK * (double)red[0] + g_l2i));
    }
}

// ---------------- launch ----------------
extern "C" void kernel_launch(void* const* d_in, const int* in_sizes, int n_in,
                              void* d_out, int out_size) {
    const int*   user       = (const int*)  d_in[0];
    const int*   item       = (const int*)  d_in[1];
    const int*   rel_rows   = (const int*)  d_in[2];
    const int*   rel_cols   = (const int*)  d_in[3];
    const int*   ig_rows    = (const int*)  d_in[4];
    const int*   ig_cols    = (const int*)  d_in[5];
    const float* ig_vals    = (const float*)d_in[6];
    const int*   train_rows = (const int*)  d_in[7];
    const int*   train_cols = (const int*)  d_in[8];
    const float* user_emb   = (const float*)d_in[9];
    const float* item_emb   = (const float*)d_in[10];
    const float* mgnn       = (const float*)d_in[11];
    const float* Wb         = (const float*)d_in[12];
    const float* Wp         = (const float*)d_in[13];
    const float* Wm         = (const float*)d_in[14];
    float* out = (float*)d_out;

    k_zero<<<(RREL*IE/4 + 255)/256, 256>>>();
    k_map<<<(BB*KK + 255)/256, 256>>>(user, item);

    {
        dim3 grid((NNZ_E/4 + 255)/256, RREL);
        k_prescan_rel<<<grid, 256>>>(rel_rows, rel_cols);
    }

    k_scatter<<<NB_SCATTER, 256>>>(ig_rows, ig_cols, ig_vals, item_emb,
                                   train_rows, train_cols, user_emb);

    k_mid<<<NB_MID, 256>>>(Wm, item_emb);

    {
        dim3 grid(BB, RREL + 1);
        k_proj<<<grid, 128>>>(Wb, Wp, Wm, mgnn);
    }

    k_score<<<(BB*KK + 255)/256, 256>>>(user, item, user_emb, item_emb, out);
    k_l2final<<<1, BB>>>(user, user_emb, out, out_size);
}